// round 13
// baseline (speedup 1.0000x reference)
#include <cuda_runtime.h>
#include <cstdint>

// ---------------------------------------------------------------------------
// GAT encoder layer, B=8, N=2048, H=1, D=256 (in_dim=256)
// out = [out(8*2048*256) | I_A(8*2048*2048)] float32
// 3 launches: k_gemm(dim3(512,2)), k_srcdst(+colmean), k_fused(zero+attn+gemm)
// ---------------------------------------------------------------------------

#define ULL unsigned long long

static const int Bn = 8;
static const int Nn = 2048;
static const int Dn = 256;

__device__ float g_h[8 * 2048 * 256];    // h = feat @ W
__device__ float g_gl[8 * 2048 * 256];   // gate linear = feat @ Hw^T
__device__ float g_asrc[8 * 2048];
__device__ float g_adst[8 * 2048];
__device__ float g_cm[8 * 256];          // column SUM of h (per batch); /2048 at use

__device__ __forceinline__ ULL pk(float x) {
    unsigned u = __float_as_uint(x);
    return ((ULL)u << 32) | (ULL)u;
}
__device__ __forceinline__ float2 upk(ULL v) {
    return make_float2(__uint_as_float((unsigned)(v & 0xffffffffu)),
                       __uint_as_float((unsigned)(v >> 32)));
}
// packed dual-fp32 FMA (FFMA2 on sm_103a)
#define FMA2(c, a, b) asm("fma.rn.f32x2 %0, %1, %2, %0;" : "+l"(c) : "l"(a), "l"(b))

#define CP_ASYNC16(dst_u32, src_ptr) \
    asm volatile("cp.async.cg.shared.global [%0], [%1], 16;" :: "r"(dst_u32), "l"(src_ptr))
#define CP_COMMIT() asm volatile("cp.async.commit_group;")
#define CP_WAIT1() asm volatile("cp.async.wait_group 1;")
#define CP_WAIT0() asm volatile("cp.async.wait_group 0;")

// ---------------------------------------------------------------------------
// K0: C[row, :256] = feat[row, :256] @ Bm  (mode 0: Bm=W row-major [k][d];
//     mode 1: Bm=Hw with out[d] = sum_k feat[k]*Hw[d][k])
// Block (0,0) also zeroes g_cm (consumed 2 kernels later; replay-safe).
// ---------------------------------------------------------------------------
__global__ __launch_bounds__(256) void k_gemm(const float* __restrict__ feat,
                                              const float* __restrict__ W,
                                              const float* __restrict__ Hw) {
    __shared__ float A_T[32][36];    // A_T[kk][ii]
    __shared__ float B_s[32][260];   // B_s[kk][d]
    const int mode = blockIdx.y;
    const float* Bm = mode ? Hw : W;
    float* C = mode ? g_gl : g_h;
    const int row0 = blockIdx.x * 32;
    const int tid = threadIdx.x;
    const int r = tid & 7, c = tid >> 3;

    if (blockIdx.x == 0 && mode == 0) {
#pragma unroll
        for (int q = 0; q < 8; q++) g_cm[q * 256 + tid] = 0.f;
    }

    ULL acc[16];
#pragma unroll
    for (int i = 0; i < 16; i++) acc[i] = 0ULL;

    for (int k0 = 0; k0 < 256; k0 += 32) {
        __syncthreads();
        {
            int ii = tid >> 3, kq = (tid & 7) * 4;
            float4 v = *(const float4*)&feat[(size_t)(row0 + ii) * 256 + k0 + kq];
            A_T[kq][ii] = v.x; A_T[kq + 1][ii] = v.y;
            A_T[kq + 2][ii] = v.z; A_T[kq + 3][ii] = v.w;
        }
        if (mode == 0) {
            for (int v = tid; v < 2048; v += 256) {
                int kk = v >> 6, q = v & 63;
                *(float4*)&B_s[kk][q * 4] =
                    *(const float4*)&Bm[(size_t)(k0 + kk) * 256 + q * 4];
            }
        } else {
            for (int v = tid; v < 8192; v += 256) {
                int d = v >> 5, kk = v & 31;
                B_s[kk][d] = Bm[(size_t)d * 256 + k0 + kk];
            }
        }
        __syncthreads();
#pragma unroll 4
        for (int kk = 0; kk < 32; kk++) {
            float4 a4 = *(const float4*)&A_T[kk][r * 4];
            ULL a0 = pk(a4.x), a1 = pk(a4.y), a2 = pk(a4.z), a3 = pk(a4.w);
            ulonglong2 b01 = *(const ulonglong2*)&B_s[kk][c * 8];
            ulonglong2 b23 = *(const ulonglong2*)&B_s[kk][c * 8 + 4];
            FMA2(acc[0],  b01.x, a0); FMA2(acc[1],  b01.y, a0);
            FMA2(acc[2],  b23.x, a0); FMA2(acc[3],  b23.y, a0);
            FMA2(acc[4],  b01.x, a1); FMA2(acc[5],  b01.y, a1);
            FMA2(acc[6],  b23.x, a1); FMA2(acc[7],  b23.y, a1);
            FMA2(acc[8],  b01.x, a2); FMA2(acc[9],  b01.y, a2);
            FMA2(acc[10], b23.x, a2); FMA2(acc[11], b23.y, a2);
            FMA2(acc[12], b01.x, a3); FMA2(acc[13], b01.y, a3);
            FMA2(acc[14], b23.x, a3); FMA2(acc[15], b23.y, a3);
        }
    }
#pragma unroll
    for (int q = 0; q < 4; q++) {
        int row = row0 + r * 4 + q;
        float2 v0 = upk(acc[q * 4 + 0]), v1 = upk(acc[q * 4 + 1]);
        float2 v2 = upk(acc[q * 4 + 2]), v3 = upk(acc[q * 4 + 3]);
        *(float4*)&C[(size_t)row * 256 + c * 8] = make_float4(v0.x, v0.y, v1.x, v1.y);
        *(float4*)&C[(size_t)row * 256 + c * 8 + 4] = make_float4(v2.x, v2.y, v3.x, v3.y);
    }
}

// ---------------------------------------------------------------------------
// K1: a_src / a_dst = h . ws_src / ws_dst ; also accumulates column sums of h
// into g_cm via block-level smem reduction + global atomics.
// ---------------------------------------------------------------------------
__global__ __launch_bounds__(256) void k_srcdst(const float* __restrict__ Ws) {
    __shared__ float ws[512];
    __shared__ float cm_s[256];
    for (int v = threadIdx.x; v < 512; v += 256) ws[v] = Ws[v];
    cm_s[threadIdx.x] = 0.f;
    __syncthreads();
    int warp = threadIdx.x >> 5, lane = threadIdx.x & 31;
    float4 s0 = *(const float4*)&ws[lane * 8];
    float4 s1 = *(const float4*)&ws[lane * 8 + 4];
    float4 t0 = *(const float4*)&ws[256 + lane * 8];
    float4 t1 = *(const float4*)&ws[256 + lane * 8 + 4];
    float cm0 = 0.f, cm1 = 0.f, cm2 = 0.f, cm3 = 0.f;
    float cm4 = 0.f, cm5 = 0.f, cm6 = 0.f, cm7 = 0.f;
    for (int it = 0; it < 16; it++) {
        int row = (blockIdx.x * 8 + warp) * 16 + it;
        const float4* hp = (const float4*)&g_h[(size_t)row * 256 + lane * 8];
        float4 v0 = hp[0], v1 = hp[1];
        cm0 += v0.x; cm1 += v0.y; cm2 += v0.z; cm3 += v0.w;
        cm4 += v1.x; cm5 += v1.y; cm6 += v1.z; cm7 += v1.w;
        float ss = v0.x * s0.x + v0.y * s0.y + v0.z * s0.z + v0.w * s0.w +
                   v1.x * s1.x + v1.y * s1.y + v1.z * s1.z + v1.w * s1.w;
        float dd = v0.x * t0.x + v0.y * t0.y + v0.z * t0.z + v0.w * t0.w +
                   v1.x * t1.x + v1.y * t1.y + v1.z * t1.z + v1.w * t1.w;
#pragma unroll
        for (int o = 16; o; o >>= 1) {
            ss += __shfl_xor_sync(0xffffffffu, ss, o);
            dd += __shfl_xor_sync(0xffffffffu, dd, o);
        }
        if (lane == 0) { g_asrc[row] = ss; g_adst[row] = dd; }
    }
    atomicAdd(&cm_s[lane * 8 + 0], cm0); atomicAdd(&cm_s[lane * 8 + 1], cm1);
    atomicAdd(&cm_s[lane * 8 + 2], cm2); atomicAdd(&cm_s[lane * 8 + 3], cm3);
    atomicAdd(&cm_s[lane * 8 + 4], cm4); atomicAdd(&cm_s[lane * 8 + 5], cm5);
    atomicAdd(&cm_s[lane * 8 + 6], cm6); atomicAdd(&cm_s[lane * 8 + 7], cm7);
    __syncthreads();
    int b = blockIdx.x >> 4;
    atomicAdd(&g_cm[b * 256 + threadIdx.x], cm_s[threadIdx.x]);
}

// ---------------------------------------------------------------------------
// K2: FUSED zero-upper + attention + I_A + triangular GEMM + epilogue.
// 512 blocks x 128 threads, 3 CTAs/SM. Block = 32 i-rows (b = bid&7,
// t = 63-(bid>>3), heavy-first). ntiles = t+1 j-tiles of 32.
// Thread roles: p-phase (ii = tid>>2 row, jq = tid&3 j-octet);
//               FMA   (r = tid&3 -> 8 i-rows, c = tid>>2 -> 8 d-cols).
// Thread tile 8i x 8d = 32 FMA2 per jj from 4 LDS.128 (balanced LDS:FMA).
// ---------------------------------------------------------------------------
__global__ __launch_bounds__(128, 3) void k_fused(
    const float* __restrict__ feat, const int* __restrict__ adj,
    const float* __restrict__ bbias, const float* __restrict__ bsp,
    const float* __restrict__ Hb,
    float* __restrict__ out, float* __restrict__ IA) {
    extern __shared__ float sm[];
    float* h_s = sm;                       // 2 * 32 * 256 floats (65536 B)
    float* p_T = sm + 2 * 32 * 256;        // 2 * 32 * 36 (p_T[buf][jj][ii])
    float* l_s = p_T + 2 * 32 * 36;        // 32

    const int tid = threadIdx.x;
    const int b = blockIdx.x & 7;
    const int t = 63 - (blockIdx.x >> 3);   // heavy blocks first
    const int r = tid & 3, c = tid >> 2;    // FMA mapping
    const int ii = tid >> 2, jq = tid & 3;  // p-phase mapping

    const unsigned h_sbase = (unsigned)__cvta_generic_to_shared(h_s);

    const int i0 = t * 32;
    const int ig = i0 + ii;
    const int ntiles = t + 1;
    const float* hsrc0 = g_h + ((size_t)b * 2048) * 256;
    const int4* adjrow = (const int4*)(adj + ((size_t)b * 2048 + ig) * 2048);
    const float4* adp = (const float4*)(g_adst + b * 2048);
    float* iarow = IA + ((size_t)b * 2048 + ig) * 2048;
    const float asrc_i = g_asrc[b * 2048 + ig];
    const float bs0 = bsp[0];
    float lsum = 0.f;

    ULL acc[32];
#pragma unroll
    for (int i = 0; i < 32; i++) acc[i] = 0ULL;

    // prologue: stage h tile 0 into buffer 0 (2048 float4, 16 per thread)
    {
        const float* src = hsrc0;
#pragma unroll
        for (int q = 0; q < 16; q++)
            CP_ASYNC16(h_sbase + (unsigned)((tid + q * 128) * 16),
                       src + (tid + q * 128) * 4);
        CP_COMMIT();
    }
    // zero strictly-upper I_A tail for this block's rows (overlaps cp.async)
    {
        float4 z = make_float4(0.f, 0.f, 0.f, 0.f);
        float4* rowp = (float4*)iarow;
        for (int j4 = ntiles * 8 + jq; j4 < 512; j4 += 4)
            rowp[j4] = z;
    }
    int4 ac0 = adjrow[jq * 2], ac1 = adjrow[jq * 2 + 1];
    float4 ad0 = adp[jq * 2], ad1 = adp[jq * 2 + 1];

    for (int kt = 0; kt < ntiles; kt++) {
        const int cb = kt & 1, nb = (kt + 1) & 1;
        __syncthreads();  // all threads done computing on buffer nb
        if (kt + 1 < ntiles) {
            const float* src = hsrc0 + (size_t)(kt + 1) * 32 * 256;
#pragma unroll
            for (int q = 0; q < 16; q++)
                CP_ASYNC16(h_sbase + (unsigned)((nb * 2048 + tid + q * 128) * 16),
                           src + (tid + q * 128) * 4);
            CP_COMMIT();
            CP_WAIT1();
        } else {
            CP_WAIT0();
        }
        // p-phase: sigmoid attention, I_A tile write, p into smem, lsum
        {
            float* pt = p_T + cb * (32 * 36);
            const int jbase = kt * 32 + jq * 8;
            const int av[8] = {ac0.x, ac0.y, ac0.z, ac0.w,
                               ac1.x, ac1.y, ac1.z, ac1.w};
            const float ad[8] = {ad0.x, ad0.y, ad0.z, ad0.w,
                                 ad1.x, ad1.y, ad1.z, ad1.w};
            float iav[8];
#pragma unroll
            for (int e = 0; e < 8; e++) {
                int jg = jbase + e;
                float x = asrc_i + ad[e] + bs0;
                float att = __fdividef(1.f, 1.f + __expf(-x));
                float ia = (jg < ig) ? -att : ((jg == ig) ? 1.f : 0.f);
                iav[e] = ia;
                float p = (jg <= ig && av[e] == 1) ? __expf(ia - 1.f) : 0.f;
                pt[(jq * 8 + e) * 36 + ii] = p;
                lsum += p;
            }
            *(float4*)(iarow + jbase) = make_float4(iav[0], iav[1], iav[2], iav[3]);
            *(float4*)(iarow + jbase + 4) = make_float4(iav[4], iav[5], iav[6], iav[7]);
        }
        if (kt + 1 < ntiles) {
            ac0 = adjrow[(kt + 1) * 8 + jq * 2];
            ac1 = adjrow[(kt + 1) * 8 + jq * 2 + 1];
            ad0 = adp[(kt + 1) * 8 + jq * 2];
            ad1 = adp[(kt + 1) * 8 + jq * 2 + 1];
        }
        __syncthreads();

        const float* hb = h_s + cb * 8192;
        const float* pb = p_T + cb * (32 * 36);
#pragma unroll 2
        for (int jj = 0; jj < 32; jj++) {
            ulonglong2 h01 = *(const ulonglong2*)&hb[jj * 256 + c * 8];
            ulonglong2 h23 = *(const ulonglong2*)&hb[jj * 256 + c * 8 + 4];
            float4 pv0 = *(const float4*)&pb[jj * 36 + r * 8];
            float4 pv1 = *(const float4*)&pb[jj * 36 + r * 8 + 4];
            ULL p0 = pk(pv0.x), p1 = pk(pv0.y), p2 = pk(pv0.z), p3 = pk(pv0.w);
            ULL p4 = pk(pv1.x), p5 = pk(pv1.y), p6 = pk(pv1.z), p7 = pk(pv1.w);
            FMA2(acc[0],  h01.x, p0); FMA2(acc[1],  h01.y, p0);
            FMA2(acc[2],  h23.x, p0); FMA2(acc[3],  h23.y, p0);
            FMA2(acc[4],  h01.x, p1); FMA2(acc[5],  h01.y, p1);
            FMA2(acc[6],  h23.x, p1); FMA2(acc[7],  h23.y, p1);
            FMA2(acc[8],  h01.x, p2); FMA2(acc[9],  h01.y, p2);
            FMA2(acc[10], h23.x, p2); FMA2(acc[11], h23.y, p2);
            FMA2(acc[12], h01.x, p3); FMA2(acc[13], h01.y, p3);
            FMA2(acc[14], h23.x, p3); FMA2(acc[15], h23.y, p3);
            FMA2(acc[16], h01.x, p4); FMA2(acc[17], h01.y, p4);
            FMA2(acc[18], h23.x, p4); FMA2(acc[19], h23.y, p4);
            FMA2(acc[20], h01.x, p5); FMA2(acc[21], h01.y, p5);
            FMA2(acc[22], h23.x, p5); FMA2(acc[23], h23.y, p5);
            FMA2(acc[24], h01.x, p6); FMA2(acc[25], h01.y, p6);
            FMA2(acc[26], h23.x, p6); FMA2(acc[27], h23.y, p6);
            FMA2(acc[28], h01.x, p7); FMA2(acc[29], h01.y, p7);
            FMA2(acc[30], h23.x, p7); FMA2(acc[31], h23.y, p7);
        }
    }

    // reduce row sums: 4 partials per row (xor over jq bits, within warp)
    lsum += __shfl_xor_sync(0xffffffffu, lsum, 1);
    lsum += __shfl_xor_sync(0xffffffffu, lsum, 2);
    if (jq == 0) l_s[ii] = lsum;
    __syncthreads();

    // epilogue: normalize, elu, highway gate, write out (8 rows per thread)
#pragma unroll
    for (int q = 0; q < 8; q++) {
        int iq = r * 8 + q;
        int igq = i0 + iq;
        float l = l_s[iq];
        bool uni = (l == 0.f);
        float inv = uni ? 0.f : (1.f / l);
        float2 v0 = upk(acc[q * 4 + 0]), v1 = upk(acc[q * 4 + 1]);
        float2 v2 = upk(acc[q * 4 + 2]), v3 = upk(acc[q * 4 + 3]);
        float vals[8] = {v0.x, v0.y, v1.x, v1.y, v2.x, v2.y, v3.x, v3.y};
        size_t base = ((size_t)b * 2048 + igq) * 256 + c * 8;
        float4 g0 = *(const float4*)&g_gl[base];
        float4 g1 = *(const float4*)&g_gl[base + 4];
        float4 f0 = *(const float4*)&feat[base];
        float4 f1 = *(const float4*)&feat[base + 4];
        float ge[8] = {g0.x, g0.y, g0.z, g0.w, g1.x, g1.y, g1.z, g1.w};
        float fe[8] = {f0.x, f0.y, f0.z, f0.w, f1.x, f1.y, f1.z, f1.w};
        float res[8];
#pragma unroll
        for (int e = 0; e < 8; e++) {
            int dd = c * 8 + e;
            float v = uni ? g_cm[b * 256 + dd] * (1.f / 2048.f) : vals[e] * inv;
            v += bbias[dd];
            float fo = v > 0.f ? v : expm1f(v);
            float gx = ge[e] + Hb[dd];
            float gate = __fdividef(1.f, 1.f + __expf(-gx));
            res[e] = gate * fo + (1.f - gate) * fe[e];
        }
        *(float4*)&out[base] = make_float4(res[0], res[1], res[2], res[3]);
        *(float4*)&out[base + 4] = make_float4(res[4], res[5], res[6], res[7]);
    }
}

// ---------------------------------------------------------------------------
extern "C" void kernel_launch(void* const* d_in, const int* in_sizes, int n_in,
                              void* d_out, int out_size) {
    const float* feat = (const float*)d_in[0];
    const int* adj = (const int*)d_in[1];
    const float* W = (const float*)d_in[2];
    const float* bb = (const float*)d_in[3];
    const float* Ws = (const float*)d_in[4];
    const float* bs = (const float*)d_in[5];
    const float* Hw = (const float*)d_in[6];
    const float* Hb = (const float*)d_in[7];

    float* out = (float*)d_out;
    float* IA = out + (size_t)Bn * Nn * Dn;  // I_A follows `out` in the tuple

    k_gemm<<<dim3(512, 2), 256>>>(feat, W, Hw);
    k_srcdst<<<128, 256>>>(Ws);

    const int smem = (2 * 32 * 256 + 2 * 32 * 36 + 32) * 4;  // 74880 B
    cudaFuncSetAttribute(k_fused, cudaFuncAttributeMaxDynamicSharedMemorySize, smem);
    k_fused<<<512, 128, smem>>>(feat, adj, bb, bs, Hb, out, IA);
}

// round 15
// speedup vs baseline: 1.1508x; 1.1508x over previous
#include <cuda_runtime.h>
#include <cstdint>

// ---------------------------------------------------------------------------
// GAT encoder layer, B=8, N=2048, H=1, D=256 (in_dim=256)
// out = [out(8*2048*256) | I_A(8*2048*2048)] float32
// 4 launches: k_zero_upper, k_gemm(dim3(512,2)), k_srcdst(+colmean), k_fused
// ---------------------------------------------------------------------------

#define ULL unsigned long long

static const int Bn = 8;
static const int Nn = 2048;
static const int Dn = 256;

__device__ float g_h[8 * 2048 * 256];    // h = feat @ W
__device__ float g_gl[8 * 2048 * 256];   // gate linear = feat @ Hw^T
__device__ float g_asrc[8 * 2048];
__device__ float g_adst[8 * 2048];
__device__ float g_cm[8 * 256];          // column SUM of h (per batch); /2048 at use

__device__ __forceinline__ ULL pk(float x) {
    unsigned u = __float_as_uint(x);
    return ((ULL)u << 32) | (ULL)u;
}
__device__ __forceinline__ float2 upk(ULL v) {
    return make_float2(__uint_as_float((unsigned)(v & 0xffffffffu)),
                       __uint_as_float((unsigned)(v >> 32)));
}
// packed dual-fp32 FMA (FFMA2 on sm_103a)
#define FMA2(c, a, b) asm("fma.rn.f32x2 %0, %1, %2, %0;" : "+l"(c) : "l"(a), "l"(b))

#define CP_ASYNC16(dst_u32, src_ptr) \
    asm volatile("cp.async.cg.shared.global [%0], [%1], 16;" :: "r"(dst_u32), "l"(src_ptr))
#define CP_COMMIT() asm volatile("cp.async.commit_group;")
#define CP_WAIT1() asm volatile("cp.async.wait_group 1;")
#define CP_WAIT0() asm volatile("cp.async.wait_group 0;")

// ---------------------------------------------------------------------------
// KZ: zero the strictly-upper j-tiles of I_A (j >= (i_tile+1)*32).
// ---------------------------------------------------------------------------
__global__ __launch_bounds__(256) void k_zero_upper(float* __restrict__ IA) {
    const int b = blockIdx.x >> 5;
    const int kp = blockIdx.x & 31;
    const int warp = threadIdx.x >> 5, lane = threadIdx.x & 31;
    float4 z = make_float4(0.f, 0.f, 0.f, 0.f);
    for (int rep = 0; rep < 2; rep++) {
        const int it = rep ? (63 - kp) : kp;
        const int i0 = it * 32;
#pragma unroll
        for (int rr = 0; rr < 4; rr++) {
            const int ig = i0 + warp * 4 + rr;
            float4* rowp = (float4*)(IA + ((size_t)b * 2048 + ig) * 2048);
            for (int j4 = (it + 1) * 8 + lane; j4 < 512; j4 += 32)
                rowp[j4] = z;
        }
    }
}

// ---------------------------------------------------------------------------
// K0: C[row, :256] = feat[row, :256] @ Bm  (mode 0: Bm=W row-major [k][d];
//     mode 1: Bm=Hw with out[d] = sum_k feat[k]*Hw[d][k])
// 128 threads, thread tile 8i x 8d (32 FMA2 per kk from 2 B-LDS.128 +
// broadcast A loads -> FMA-bound, not LDS-bound).
// Block (0,0) also zeroes g_cm (consumed 2 kernels later; replay-safe).
// ---------------------------------------------------------------------------
__global__ __launch_bounds__(128, 4) void k_gemm(const float* __restrict__ feat,
                                                 const float* __restrict__ W,
                                                 const float* __restrict__ Hw) {
    __shared__ float A_T[32][36];    // A_T[kk][ii]
    __shared__ float B_s[32][260];   // B_s[kk][d]
    const int mode = blockIdx.y;
    const float* Bm = mode ? Hw : W;
    float* C = mode ? g_gl : g_h;
    const int row0 = blockIdx.x * 32;
    const int tid = threadIdx.x;
    const int r = tid & 3, c = tid >> 2;   // 4 i-groups of 8 rows, 32 d-groups of 8

    if (blockIdx.x == 0 && mode == 0) {
#pragma unroll
        for (int q = 0; q < 16; q++) g_cm[q * 128 + tid] = 0.f;
    }

    ULL acc[32];
#pragma unroll
    for (int i = 0; i < 32; i++) acc[i] = 0ULL;

    for (int k0 = 0; k0 < 256; k0 += 32) {
        __syncthreads();
        // A tile: 32 rows x 32 k -> A_T[kk][ii]; 256 float4, 2 per thread
#pragma unroll
        for (int q = 0; q < 2; q++) {
            int v = tid + q * 128;
            int ii = v >> 3, kq = (v & 7) * 4;
            float4 x = *(const float4*)&feat[(size_t)(row0 + ii) * 256 + k0 + kq];
            A_T[kq][ii] = x.x; A_T[kq + 1][ii] = x.y;
            A_T[kq + 2][ii] = x.z; A_T[kq + 3][ii] = x.w;
        }
        if (mode == 0) {
#pragma unroll
            for (int q = 0; q < 16; q++) {
                int v = tid + q * 128;
                int kk = v >> 6, f4 = v & 63;
                *(float4*)&B_s[kk][f4 * 4] =
                    *(const float4*)&Bm[(size_t)(k0 + kk) * 256 + f4 * 4];
            }
        } else {
            for (int v = tid; v < 8192; v += 128) {
                int d = v >> 5, kk = v & 31;
                B_s[kk][d] = Bm[(size_t)d * 256 + k0 + kk];
            }
        }
        __syncthreads();
#pragma unroll 2
        for (int kk = 0; kk < 32; kk++) {
            float4 a40 = *(const float4*)&A_T[kk][r * 8];
            float4 a41 = *(const float4*)&A_T[kk][r * 8 + 4];
            ULL a0 = pk(a40.x), a1 = pk(a40.y), a2 = pk(a40.z), a3 = pk(a40.w);
            ULL a4 = pk(a41.x), a5 = pk(a41.y), a6 = pk(a41.z), a7 = pk(a41.w);
            ulonglong2 b01 = *(const ulonglong2*)&B_s[kk][c * 8];
            ulonglong2 b23 = *(const ulonglong2*)&B_s[kk][c * 8 + 4];
            FMA2(acc[0],  b01.x, a0); FMA2(acc[1],  b01.y, a0);
            FMA2(acc[2],  b23.x, a0); FMA2(acc[3],  b23.y, a0);
            FMA2(acc[4],  b01.x, a1); FMA2(acc[5],  b01.y, a1);
            FMA2(acc[6],  b23.x, a1); FMA2(acc[7],  b23.y, a1);
            FMA2(acc[8],  b01.x, a2); FMA2(acc[9],  b01.y, a2);
            FMA2(acc[10], b23.x, a2); FMA2(acc[11], b23.y, a2);
            FMA2(acc[12], b01.x, a3); FMA2(acc[13], b01.y, a3);
            FMA2(acc[14], b23.x, a3); FMA2(acc[15], b23.y, a3);
            FMA2(acc[16], b01.x, a4); FMA2(acc[17], b01.y, a4);
            FMA2(acc[18], b23.x, a4); FMA2(acc[19], b23.y, a4);
            FMA2(acc[20], b01.x, a5); FMA2(acc[21], b01.y, a5);
            FMA2(acc[22], b23.x, a5); FMA2(acc[23], b23.y, a5);
            FMA2(acc[24], b01.x, a6); FMA2(acc[25], b01.y, a6);
            FMA2(acc[26], b23.x, a6); FMA2(acc[27], b23.y, a6);
            FMA2(acc[28], b01.x, a7); FMA2(acc[29], b01.y, a7);
            FMA2(acc[30], b23.x, a7); FMA2(acc[31], b23.y, a7);
        }
    }
#pragma unroll
    for (int q = 0; q < 8; q++) {
        int row = row0 + r * 8 + q;
        float2 v0 = upk(acc[q * 4 + 0]), v1 = upk(acc[q * 4 + 1]);
        float2 v2 = upk(acc[q * 4 + 2]), v3 = upk(acc[q * 4 + 3]);
        *(float4*)&C[(size_t)row * 256 + c * 8] = make_float4(v0.x, v0.y, v1.x, v1.y);
        *(float4*)&C[(size_t)row * 256 + c * 8 + 4] = make_float4(v2.x, v2.y, v3.x, v3.y);
    }
}

// ---------------------------------------------------------------------------
// K1: a_src / a_dst = h . ws_src / ws_dst ; also accumulates column sums of h
// into g_cm via block-level smem reduction + global atomics.
// ---------------------------------------------------------------------------
__global__ __launch_bounds__(256) void k_srcdst(const float* __restrict__ Ws) {
    __shared__ float ws[512];
    __shared__ float cm_s[256];
    for (int v = threadIdx.x; v < 512; v += 256) ws[v] = Ws[v];
    cm_s[threadIdx.x] = 0.f;
    __syncthreads();
    int warp = threadIdx.x >> 5, lane = threadIdx.x & 31;
    float4 s0 = *(const float4*)&ws[lane * 8];
    float4 s1 = *(const float4*)&ws[lane * 8 + 4];
    float4 t0 = *(const float4*)&ws[256 + lane * 8];
    float4 t1 = *(const float4*)&ws[256 + lane * 8 + 4];
    float cm0 = 0.f, cm1 = 0.f, cm2 = 0.f, cm3 = 0.f;
    float cm4 = 0.f, cm5 = 0.f, cm6 = 0.f, cm7 = 0.f;
    for (int it = 0; it < 16; it++) {
        int row = (blockIdx.x * 8 + warp) * 16 + it;
        const float4* hp = (const float4*)&g_h[(size_t)row * 256 + lane * 8];
        float4 v0 = hp[0], v1 = hp[1];
        cm0 += v0.x; cm1 += v0.y; cm2 += v0.z; cm3 += v0.w;
        cm4 += v1.x; cm5 += v1.y; cm6 += v1.z; cm7 += v1.w;
        float ss = v0.x * s0.x + v0.y * s0.y + v0.z * s0.z + v0.w * s0.w +
                   v1.x * s1.x + v1.y * s1.y + v1.z * s1.z + v1.w * s1.w;
        float dd = v0.x * t0.x + v0.y * t0.y + v0.z * t0.z + v0.w * t0.w +
                   v1.x * t1.x + v1.y * t1.y + v1.z * t1.z + v1.w * t1.w;
#pragma unroll
        for (int o = 16; o; o >>= 1) {
            ss += __shfl_xor_sync(0xffffffffu, ss, o);
            dd += __shfl_xor_sync(0xffffffffu, dd, o);
        }
        if (lane == 0) { g_asrc[row] = ss; g_adst[row] = dd; }
    }
    atomicAdd(&cm_s[lane * 8 + 0], cm0); atomicAdd(&cm_s[lane * 8 + 1], cm1);
    atomicAdd(&cm_s[lane * 8 + 2], cm2); atomicAdd(&cm_s[lane * 8 + 3], cm3);
    atomicAdd(&cm_s[lane * 8 + 4], cm4); atomicAdd(&cm_s[lane * 8 + 5], cm5);
    atomicAdd(&cm_s[lane * 8 + 6], cm6); atomicAdd(&cm_s[lane * 8 + 7], cm7);
    __syncthreads();
    int b = blockIdx.x >> 4;
    atomicAdd(&g_cm[b * 256 + threadIdx.x], cm_s[threadIdx.x]);
}

// ---------------------------------------------------------------------------
// K2: FUSED attention + I_A + triangular GEMM + epilogue (R11 config).
// 512 blocks x 256 threads, 2 CTAs/SM. Block = 32 i-rows (b = bid&7,
// t = 63-(bid>>3), heavy-first). ntiles = t+1 j-tiles of 32.
// ---------------------------------------------------------------------------
__global__ __launch_bounds__(256, 2) void k_fused(
    const float* __restrict__ feat, const int* __restrict__ adj,
    const float* __restrict__ bbias, const float* __restrict__ bsp,
    const float* __restrict__ Hb,
    float* __restrict__ out, float* __restrict__ IA) {
    extern __shared__ float sm[];
    float* h_s = sm;                       // 2 * 32 * 256 floats
    float* p_T = sm + 2 * 32 * 256;        // 2 * 32 * 36 (p_T[buf][jj][ii])
    float* l_s = p_T + 2 * 32 * 36;        // 32

    const int tid = threadIdx.x;
    const int b = blockIdx.x & 7;
    const int t = 63 - (blockIdx.x >> 3);   // heavy blocks first
    const int r = tid & 7, c = tid >> 3;
    const int ii = tid >> 3, jq = tid & 7;  // p-phase mapping

    const unsigned h_sbase = (unsigned)__cvta_generic_to_shared(h_s);

    const int i0 = t * 32;
    const int ig = i0 + ii;
    const int ntiles = t + 1;
    const float* hsrc0 = g_h + ((size_t)b * 2048) * 256;
    const int4* adjrow = (const int4*)(adj + ((size_t)b * 2048 + ig) * 2048);
    const float4* adp = (const float4*)(g_adst + b * 2048);
    float* iarow = IA + ((size_t)b * 2048 + ig) * 2048;
    const float asrc_i = g_asrc[b * 2048 + ig];
    const float bs0 = bsp[0];
    float lsum = 0.f;

    ULL acc[16];
#pragma unroll
    for (int i = 0; i < 16; i++) acc[i] = 0ULL;

    // prologue: stage h tile 0 into buffer 0
    {
        const float* src = hsrc0;
#pragma unroll
        for (int q = 0; q < 8; q++)
            CP_ASYNC16(h_sbase + (unsigned)((tid + q * 256) * 16),
                       src + (tid + q * 256) * 4);
        CP_COMMIT();
    }
    int4 acur = adjrow[jq];
    float4 adcur = adp[jq];

    for (int kt = 0; kt < ntiles; kt++) {
        const int cb = kt & 1, nb = (kt + 1) & 1;
        __syncthreads();  // all threads done computing on buffer nb
        if (kt + 1 < ntiles) {
            const float* src = hsrc0 + (size_t)(kt + 1) * 32 * 256;
#pragma unroll
            for (int q = 0; q < 8; q++)
                CP_ASYNC16(h_sbase + (unsigned)((nb * 2048 + tid + q * 256) * 16),
                           src + (tid + q * 256) * 4);
            CP_COMMIT();
            CP_WAIT1();
        } else {
            CP_WAIT0();
        }
        // p-phase: sigmoid attention, I_A tile write, p into smem, lsum
        {
            float* pt = p_T + cb * (32 * 36);
            const int jbase = kt * 32 + jq * 4;
            const int av[4] = {acur.x, acur.y, acur.z, acur.w};
            const float ad[4] = {adcur.x, adcur.y, adcur.z, adcur.w};
            float iav[4];
#pragma unroll
            for (int e = 0; e < 4; e++) {
                int jg = jbase + e;
                float x = asrc_i + ad[e] + bs0;
                float att = __fdividef(1.f, 1.f + __expf(-x));
                float ia = (jg < ig) ? -att : ((jg == ig) ? 1.f : 0.f);
                iav[e] = ia;
                float p = (jg <= ig && av[e] == 1) ? __expf(ia - 1.f) : 0.f;
                pt[(jq * 4 + e) * 36 + ii] = p;
                lsum += p;
            }
            *(float4*)(iarow + jbase) = make_float4(iav[0], iav[1], iav[2], iav[3]);
        }
        if (kt + 1 < ntiles) {
            acur = adjrow[(kt + 1) * 8 + jq];
            adcur = adp[(kt + 1) * 8 + jq];
        }
        __syncthreads();

        const float* hb = h_s + cb * 8192;
        const float* pb = p_T + cb * (32 * 36);
#pragma unroll 4
        for (int jj = 0; jj < 32; jj++) {
            ulonglong2 h01 = *(const ulonglong2*)&hb[jj * 256 + c * 8];
            ulonglong2 h23 = *(const ulonglong2*)&hb[jj * 256 + c * 8 + 4];
            float4 pv = *(const float4*)&pb[jj * 36 + r * 4];
            ULL p0 = pk(pv.x), p1 = pk(pv.y), p2 = pk(pv.z), p3 = pk(pv.w);
            FMA2(acc[0],  h01.x, p0); FMA2(acc[1],  h01.y, p0);
            FMA2(acc[2],  h23.x, p0); FMA2(acc[3],  h23.y, p0);
            FMA2(acc[4],  h01.x, p1); FMA2(acc[5],  h01.y, p1);
            FMA2(acc[6],  h23.x, p1); FMA2(acc[7],  h23.y, p1);
            FMA2(acc[8],  h01.x, p2); FMA2(acc[9],  h01.y, p2);
            FMA2(acc[10], h23.x, p2); FMA2(acc[11], h23.y, p2);
            FMA2(acc[12], h01.x, p3); FMA2(acc[13], h01.y, p3);
            FMA2(acc[14], h23.x, p3); FMA2(acc[15], h23.y, p3);
        }
    }

    // reduce row sums: 8 partials per row live in one warp (xor over jq bits)
#pragma unroll
    for (int o = 1; o < 8; o <<= 1)
        lsum += __shfl_xor_sync(0xffffffffu, lsum, o);
    if (jq == 0) l_s[ii] = lsum;
    __syncthreads();

    // epilogue: normalize, elu, highway gate, write out
#pragma unroll
    for (int q = 0; q < 4; q++) {
        int iq = r * 4 + q;
        int igq = i0 + iq;
        float l = l_s[iq];
        bool uni = (l == 0.f);
        float inv = uni ? 0.f : (1.f / l);
        float2 v0 = upk(acc[q * 4 + 0]), v1 = upk(acc[q * 4 + 1]);
        float2 v2 = upk(acc[q * 4 + 2]), v3 = upk(acc[q * 4 + 3]);
        float vals[8] = {v0.x, v0.y, v1.x, v1.y, v2.x, v2.y, v3.x, v3.y};
        size_t base = ((size_t)b * 2048 + igq) * 256 + c * 8;
        float4 g0 = *(const float4*)&g_gl[base];
        float4 g1 = *(const float4*)&g_gl[base + 4];
        float4 f0 = *(const float4*)&feat[base];
        float4 f1 = *(const float4*)&feat[base + 4];
        float ge[8] = {g0.x, g0.y, g0.z, g0.w, g1.x, g1.y, g1.z, g1.w};
        float fe[8] = {f0.x, f0.y, f0.z, f0.w, f1.x, f1.y, f1.z, f1.w};
        float res[8];
#pragma unroll
        for (int e = 0; e < 8; e++) {
            int dd = c * 8 + e;
            float v = uni ? g_cm[b * 256 + dd] * (1.f / 2048.f) : vals[e] * inv;
            v += bbias[dd];
            float fo = v > 0.f ? v : expm1f(v);
            float gx = ge[e] + Hb[dd];
            float gate = __fdividef(1.f, 1.f + __expf(-gx));
            res[e] = gate * fo + (1.f - gate) * fe[e];
        }
        *(float4*)&out[base] = make_float4(res[0], res[1], res[2], res[3]);
        *(float4*)&out[base + 4] = make_float4(res[4], res[5], res[6], res[7]);
    }
}

// ---------------------------------------------------------------------------
extern "C" void kernel_launch(void* const* d_in, const int* in_sizes, int n_in,
                              void* d_out, int out_size) {
    const float* feat = (const float*)d_in[0];
    const int* adj = (const int*)d_in[1];
    const float* W = (const float*)d_in[2];
    const float* bb = (const float*)d_in[3];
    const float* Ws = (const float*)d_in[4];
    const float* bs = (const float*)d_in[5];
    const float* Hw = (const float*)d_in[6];
    const float* Hb = (const float*)d_in[7];

    float* out = (float*)d_out;
    float* IA = out + (size_t)Bn * Nn * Dn;  // I_A follows `out` in the tuple

    k_zero_upper<<<256, 256>>>(IA);
    k_gemm<<<dim3(512, 2), 128>>>(feat, W, Hw);
    k_srcdst<<<128, 256>>>(Ws);

    const int smem = (2 * 32 * 256 + 2 * 32 * 36 + 32) * 4;  // 74880 B
    cudaFuncSetAttribute(k_fused, cudaFuncAttributeMaxDynamicSharedMemorySize, smem);
    k_fused<<<512, 256, smem>>>(feat, adj, bb, bs, Hb, out, IA);
}

// round 16
// speedup vs baseline: 1.1513x; 1.0004x over previous
#include <cuda_runtime.h>
#include <cstdint>

// ---------------------------------------------------------------------------
// GAT encoder layer, B=8, N=2048, H=1, D=256 (in_dim=256)
// out = [out(8*2048*256) | I_A(8*2048*2048)] float32
// 4 launches: k_zero_upper, k_gemm(dim3(512,2)), k_srcdst(+colmean), k_fused
// ---------------------------------------------------------------------------

#define ULL unsigned long long

static const int Bn = 8;
static const int Nn = 2048;
static const int Dn = 256;

__device__ float g_h[8 * 2048 * 256];    // h = feat @ W
__device__ float g_gl[8 * 2048 * 256];   // gate linear = feat @ Hw^T
__device__ float g_asrc[8 * 2048];
__device__ float g_adst[8 * 2048];
__device__ float g_cm[8 * 256];          // column SUM of h (per batch); /2048 at use

__device__ __forceinline__ ULL pk(float x) {
    unsigned u = __float_as_uint(x);
    return ((ULL)u << 32) | (ULL)u;
}
__device__ __forceinline__ float2 upk(ULL v) {
    return make_float2(__uint_as_float((unsigned)(v & 0xffffffffu)),
                       __uint_as_float((unsigned)(v >> 32)));
}
// packed dual-fp32 FMA (FFMA2 on sm_103a)
#define FMA2(c, a, b) asm("fma.rn.f32x2 %0, %1, %2, %0;" : "+l"(c) : "l"(a), "l"(b))

#define CP_ASYNC16(dst_u32, src_ptr) \
    asm volatile("cp.async.cg.shared.global [%0], [%1], 16;" :: "r"(dst_u32), "l"(src_ptr))
#define CP_COMMIT() asm volatile("cp.async.commit_group;")
#define CP_WAIT1() asm volatile("cp.async.wait_group 1;")
#define CP_WAIT0() asm volatile("cp.async.wait_group 0;")

// ---------------------------------------------------------------------------
// KZ: zero the strictly-upper j-tiles of I_A (j >= (i_tile+1)*32).
// ---------------------------------------------------------------------------
__global__ __launch_bounds__(256) void k_zero_upper(float* __restrict__ IA) {
    const int b = blockIdx.x >> 5;
    const int kp = blockIdx.x & 31;
    const int warp = threadIdx.x >> 5, lane = threadIdx.x & 31;
    float4 z = make_float4(0.f, 0.f, 0.f, 0.f);
    for (int rep = 0; rep < 2; rep++) {
        const int it = rep ? (63 - kp) : kp;
        const int i0 = it * 32;
#pragma unroll
        for (int rr = 0; rr < 4; rr++) {
            const int ig = i0 + warp * 4 + rr;
            float4* rowp = (float4*)(IA + ((size_t)b * 2048 + ig) * 2048);
            for (int j4 = (it + 1) * 8 + lane; j4 < 512; j4 += 32)
                rowp[j4] = z;
        }
    }
}

// ---------------------------------------------------------------------------
// K0: C[row, :256] = feat[row, :256] @ Bm  (mode 0: Bm=W row-major [k][d];
//     mode 1: Bm=Hw with out[d] = sum_k feat[k]*Hw[d][k])
// 128 threads, thread tile 8i x 8d (32 FMA2 per kk from 2 B-LDS.128 +
// broadcast A loads -> FMA-bound, not LDS-bound).
// Block (0,0) also zeroes g_cm (consumed 2 kernels later; replay-safe).
// ---------------------------------------------------------------------------
__global__ __launch_bounds__(128, 4) void k_gemm(const float* __restrict__ feat,
                                                 const float* __restrict__ W,
                                                 const float* __restrict__ Hw) {
    __shared__ float A_T[32][36];    // A_T[kk][ii]
    __shared__ float B_s[32][260];   // B_s[kk][d]
    const int mode = blockIdx.y;
    const float* Bm = mode ? Hw : W;
    float* C = mode ? g_gl : g_h;
    const int row0 = blockIdx.x * 32;
    const int tid = threadIdx.x;
    const int r = tid & 3, c = tid >> 2;   // 4 i-groups of 8 rows, 32 d-groups of 8

    if (blockIdx.x == 0 && mode == 0) {
#pragma unroll
        for (int q = 0; q < 16; q++) g_cm[q * 128 + tid] = 0.f;
    }

    ULL acc[32];
#pragma unroll
    for (int i = 0; i < 32; i++) acc[i] = 0ULL;

    for (int k0 = 0; k0 < 256; k0 += 32) {
        __syncthreads();
        // A tile: 32 rows x 32 k -> A_T[kk][ii]; 256 float4, 2 per thread
#pragma unroll
        for (int q = 0; q < 2; q++) {
            int v = tid + q * 128;
            int ii = v >> 3, kq = (v & 7) * 4;
            float4 x = *(const float4*)&feat[(size_t)(row0 + ii) * 256 + k0 + kq];
            A_T[kq][ii] = x.x; A_T[kq + 1][ii] = x.y;
            A_T[kq + 2][ii] = x.z; A_T[kq + 3][ii] = x.w;
        }
        if (mode == 0) {
#pragma unroll
            for (int q = 0; q < 16; q++) {
                int v = tid + q * 128;
                int kk = v >> 6, f4 = v & 63;
                *(float4*)&B_s[kk][f4 * 4] =
                    *(const float4*)&Bm[(size_t)(k0 + kk) * 256 + f4 * 4];
            }
        } else {
            for (int v = tid; v < 8192; v += 128) {
                int d = v >> 5, kk = v & 31;
                B_s[kk][d] = Bm[(size_t)d * 256 + k0 + kk];
            }
        }
        __syncthreads();
#pragma unroll 2
        for (int kk = 0; kk < 32; kk++) {
            float4 a40 = *(const float4*)&A_T[kk][r * 8];
            float4 a41 = *(const float4*)&A_T[kk][r * 8 + 4];
            ULL a0 = pk(a40.x), a1 = pk(a40.y), a2 = pk(a40.z), a3 = pk(a40.w);
            ULL a4 = pk(a41.x), a5 = pk(a41.y), a6 = pk(a41.z), a7 = pk(a41.w);
            ulonglong2 b01 = *(const ulonglong2*)&B_s[kk][c * 8];
            ulonglong2 b23 = *(const ulonglong2*)&B_s[kk][c * 8 + 4];
            FMA2(acc[0],  b01.x, a0); FMA2(acc[1],  b01.y, a0);
            FMA2(acc[2],  b23.x, a0); FMA2(acc[3],  b23.y, a0);
            FMA2(acc[4],  b01.x, a1); FMA2(acc[5],  b01.y, a1);
            FMA2(acc[6],  b23.x, a1); FMA2(acc[7],  b23.y, a1);
            FMA2(acc[8],  b01.x, a2); FMA2(acc[9],  b01.y, a2);
            FMA2(acc[10], b23.x, a2); FMA2(acc[11], b23.y, a2);
            FMA2(acc[12], b01.x, a3); FMA2(acc[13], b01.y, a3);
            FMA2(acc[14], b23.x, a3); FMA2(acc[15], b23.y, a3);
            FMA2(acc[16], b01.x, a4); FMA2(acc[17], b01.y, a4);
            FMA2(acc[18], b23.x, a4); FMA2(acc[19], b23.y, a4);
            FMA2(acc[20], b01.x, a5); FMA2(acc[21], b01.y, a5);
            FMA2(acc[22], b23.x, a5); FMA2(acc[23], b23.y, a5);
            FMA2(acc[24], b01.x, a6); FMA2(acc[25], b01.y, a6);
            FMA2(acc[26], b23.x, a6); FMA2(acc[27], b23.y, a6);
            FMA2(acc[28], b01.x, a7); FMA2(acc[29], b01.y, a7);
            FMA2(acc[30], b23.x, a7); FMA2(acc[31], b23.y, a7);
        }
    }
#pragma unroll
    for (int q = 0; q < 8; q++) {
        int row = row0 + r * 8 + q;
        float2 v0 = upk(acc[q * 4 + 0]), v1 = upk(acc[q * 4 + 1]);
        float2 v2 = upk(acc[q * 4 + 2]), v3 = upk(acc[q * 4 + 3]);
        *(float4*)&C[(size_t)row * 256 + c * 8] = make_float4(v0.x, v0.y, v1.x, v1.y);
        *(float4*)&C[(size_t)row * 256 + c * 8 + 4] = make_float4(v2.x, v2.y, v3.x, v3.y);
    }
}

// ---------------------------------------------------------------------------
// K1: a_src / a_dst = h . ws_src / ws_dst ; also accumulates column sums of h
// into g_cm via block-level smem reduction + global atomics.
// ---------------------------------------------------------------------------
__global__ __launch_bounds__(256) void k_srcdst(const float* __restrict__ Ws) {
    __shared__ float ws[512];
    __shared__ float cm_s[256];
    for (int v = threadIdx.x; v < 512; v += 256) ws[v] = Ws[v];
    cm_s[threadIdx.x] = 0.f;
    __syncthreads();
    int warp = threadIdx.x >> 5, lane = threadIdx.x & 31;
    float4 s0 = *(const float4*)&ws[lane * 8];
    float4 s1 = *(const float4*)&ws[lane * 8 + 4];
    float4 t0 = *(const float4*)&ws[256 + lane * 8];
    float4 t1 = *(const float4*)&ws[256 + lane * 8 + 4];
    float cm0 = 0.f, cm1 = 0.f, cm2 = 0.f, cm3 = 0.f;
    float cm4 = 0.f, cm5 = 0.f, cm6 = 0.f, cm7 = 0.f;
    for (int it = 0; it < 16; it++) {
        int row = (blockIdx.x * 8 + warp) * 16 + it;
        const float4* hp = (const float4*)&g_h[(size_t)row * 256 + lane * 8];
        float4 v0 = hp[0], v1 = hp[1];
        cm0 += v0.x; cm1 += v0.y; cm2 += v0.z; cm3 += v0.w;
        cm4 += v1.x; cm5 += v1.y; cm6 += v1.z; cm7 += v1.w;
        float ss = v0.x * s0.x + v0.y * s0.y + v0.z * s0.z + v0.w * s0.w +
                   v1.x * s1.x + v1.y * s1.y + v1.z * s1.z + v1.w * s1.w;
        float dd = v0.x * t0.x + v0.y * t0.y + v0.z * t0.z + v0.w * t0.w +
                   v1.x * t1.x + v1.y * t1.y + v1.z * t1.z + v1.w * t1.w;
#pragma unroll
        for (int o = 16; o; o >>= 1) {
            ss += __shfl_xor_sync(0xffffffffu, ss, o);
            dd += __shfl_xor_sync(0xffffffffu, dd, o);
        }
        if (lane == 0) { g_asrc[row] = ss; g_adst[row] = dd; }
    }
    atomicAdd(&cm_s[lane * 8 + 0], cm0); atomicAdd(&cm_s[lane * 8 + 1], cm1);
    atomicAdd(&cm_s[lane * 8 + 2], cm2); atomicAdd(&cm_s[lane * 8 + 3], cm3);
    atomicAdd(&cm_s[lane * 8 + 4], cm4); atomicAdd(&cm_s[lane * 8 + 5], cm5);
    atomicAdd(&cm_s[lane * 8 + 6], cm6); atomicAdd(&cm_s[lane * 8 + 7], cm7);
    __syncthreads();
    int b = blockIdx.x >> 4;
    atomicAdd(&g_cm[b * 256 + threadIdx.x], cm_s[threadIdx.x]);
}

// ---------------------------------------------------------------------------
// K2: FUSED attention + I_A + triangular GEMM + epilogue (R11 config).
// 512 blocks x 256 threads, 2 CTAs/SM. Block = 32 i-rows (b = bid&7,
// t = 63-(bid>>3), heavy-first). ntiles = t+1 j-tiles of 32.
// ---------------------------------------------------------------------------
__global__ __launch_bounds__(256, 2) void k_fused(
    const float* __restrict__ feat, const int* __restrict__ adj,
    const float* __restrict__ bbias, const float* __restrict__ bsp,
    const float* __restrict__ Hb,
    float* __restrict__ out, float* __restrict__ IA) {
    extern __shared__ float sm[];
    float* h_s = sm;                       // 2 * 32 * 256 floats
    float* p_T = sm + 2 * 32 * 256;        // 2 * 32 * 36 (p_T[buf][jj][ii])
    float* l_s = p_T + 2 * 32 * 36;        // 32

    const int tid = threadIdx.x;
    const int b = blockIdx.x & 7;
    const int t = 63 - (blockIdx.x >> 3);   // heavy blocks first
    const int r = tid & 7, c = tid >> 3;
    const int ii = tid >> 3, jq = tid & 7;  // p-phase mapping

    const unsigned h_sbase = (unsigned)__cvta_generic_to_shared(h_s);

    const int i0 = t * 32;
    const int ig = i0 + ii;
    const int ntiles = t + 1;
    const float* hsrc0 = g_h + ((size_t)b * 2048) * 256;
    const int4* adjrow = (const int4*)(adj + ((size_t)b * 2048 + ig) * 2048);
    const float4* adp = (const float4*)(g_adst + b * 2048);
    float* iarow = IA + ((size_t)b * 2048 + ig) * 2048;
    const float asrc_i = g_asrc[b * 2048 + ig];
    const float bs0 = bsp[0];
    float lsum = 0.f;

    ULL acc[16];
#pragma unroll
    for (int i = 0; i < 16; i++) acc[i] = 0ULL;

    // prologue: stage h tile 0 into buffer 0
    {
        const float* src = hsrc0;
#pragma unroll
        for (int q = 0; q < 8; q++)
            CP_ASYNC16(h_sbase + (unsigned)((tid + q * 256) * 16),
                       src + (tid + q * 256) * 4);
        CP_COMMIT();
    }
    int4 acur = adjrow[jq];
    float4 adcur = adp[jq];

    for (int kt = 0; kt < ntiles; kt++) {
        const int cb = kt & 1, nb = (kt + 1) & 1;
        __syncthreads();  // all threads done computing on buffer nb
        if (kt + 1 < ntiles) {
            const float* src = hsrc0 + (size_t)(kt + 1) * 32 * 256;
#pragma unroll
            for (int q = 0; q < 8; q++)
                CP_ASYNC16(h_sbase + (unsigned)((nb * 2048 + tid + q * 256) * 16),
                           src + (tid + q * 256) * 4);
            CP_COMMIT();
            CP_WAIT1();
        } else {
            CP_WAIT0();
        }
        // p-phase: sigmoid attention, I_A tile write, p into smem, lsum
        {
            float* pt = p_T + cb * (32 * 36);
            const int jbase = kt * 32 + jq * 4;
            const int av[4] = {acur.x, acur.y, acur.z, acur.w};
            const float ad[4] = {adcur.x, adcur.y, adcur.z, adcur.w};
            float iav[4];
#pragma unroll
            for (int e = 0; e < 4; e++) {
                int jg = jbase + e;
                float x = asrc_i + ad[e] + bs0;
                float att = __fdividef(1.f, 1.f + __expf(-x));
                float ia = (jg < ig) ? -att : ((jg == ig) ? 1.f : 0.f);
                iav[e] = ia;
                float p = (jg <= ig && av[e] == 1) ? __expf(ia - 1.f) : 0.f;
                pt[(jq * 4 + e) * 36 + ii] = p;
                lsum += p;
            }
            *(float4*)(iarow + jbase) = make_float4(iav[0], iav[1], iav[2], iav[3]);
        }
        if (kt + 1 < ntiles) {
            acur = adjrow[(kt + 1) * 8 + jq];
            adcur = adp[(kt + 1) * 8 + jq];
        }
        __syncthreads();

        const float* hb = h_s + cb * 8192;
        const float* pb = p_T + cb * (32 * 36);
#pragma unroll 4
        for (int jj = 0; jj < 32; jj++) {
            ulonglong2 h01 = *(const ulonglong2*)&hb[jj * 256 + c * 8];
            ulonglong2 h23 = *(const ulonglong2*)&hb[jj * 256 + c * 8 + 4];
            float4 pv = *(const float4*)&pb[jj * 36 + r * 4];
            ULL p0 = pk(pv.x), p1 = pk(pv.y), p2 = pk(pv.z), p3 = pk(pv.w);
            FMA2(acc[0],  h01.x, p0); FMA2(acc[1],  h01.y, p0);
            FMA2(acc[2],  h23.x, p0); FMA2(acc[3],  h23.y, p0);
            FMA2(acc[4],  h01.x, p1); FMA2(acc[5],  h01.y, p1);
            FMA2(acc[6],  h23.x, p1); FMA2(acc[7],  h23.y, p1);
            FMA2(acc[8],  h01.x, p2); FMA2(acc[9],  h01.y, p2);
            FMA2(acc[10], h23.x, p2); FMA2(acc[11], h23.y, p2);
            FMA2(acc[12], h01.x, p3); FMA2(acc[13], h01.y, p3);
            FMA2(acc[14], h23.x, p3); FMA2(acc[15], h23.y, p3);
        }
    }

    // reduce row sums: 8 partials per row live in one warp (xor over jq bits)
#pragma unroll
    for (int o = 1; o < 8; o <<= 1)
        lsum += __shfl_xor_sync(0xffffffffu, lsum, o);
    if (jq == 0) l_s[ii] = lsum;
    __syncthreads();

    // epilogue: normalize, elu, highway gate, write out
#pragma unroll
    for (int q = 0; q < 4; q++) {
        int iq = r * 4 + q;
        int igq = i0 + iq;
        float l = l_s[iq];
        bool uni = (l == 0.f);
        float inv = uni ? 0.f : (1.f / l);
        float2 v0 = upk(acc[q * 4 + 0]), v1 = upk(acc[q * 4 + 1]);
        float2 v2 = upk(acc[q * 4 + 2]), v3 = upk(acc[q * 4 + 3]);
        float vals[8] = {v0.x, v0.y, v1.x, v1.y, v2.x, v2.y, v3.x, v3.y};
        size_t base = ((size_t)b * 2048 + igq) * 256 + c * 8;
        float4 g0 = *(const float4*)&g_gl[base];
        float4 g1 = *(const float4*)&g_gl[base + 4];
        float4 f0 = *(const float4*)&feat[base];
        float4 f1 = *(const float4*)&feat[base + 4];
        float ge[8] = {g0.x, g0.y, g0.z, g0.w, g1.x, g1.y, g1.z, g1.w};
        float fe[8] = {f0.x, f0.y, f0.z, f0.w, f1.x, f1.y, f1.z, f1.w};
        float res[8];
#pragma unroll
        for (int e = 0; e < 8; e++) {
            int dd = c * 8 + e;
            float v = uni ? g_cm[b * 256 + dd] * (1.f / 2048.f) : vals[e] * inv;
            v += bbias[dd];
            float fo = v > 0.f ? v : expm1f(v);
            float gx = ge[e] + Hb[dd];
            float gate = __fdividef(1.f, 1.f + __expf(-gx));
            res[e] = gate * fo + (1.f - gate) * fe[e];
        }
        *(float4*)&out[base] = make_float4(res[0], res[1], res[2], res[3]);
        *(float4*)&out[base + 4] = make_float4(res[4], res[5], res[6], res[7]);
    }
}

// ---------------------------------------------------------------------------
extern "C" void kernel_launch(void* const* d_in, const int* in_sizes, int n_in,
                              void* d_out, int out_size) {
    const float* feat = (const float*)d_in[0];
    const int* adj = (const int*)d_in[1];
    const float* W = (const float*)d_in[2];
    const float* bb = (const float*)d_in[3];
    const float* Ws = (const float*)d_in[4];
    const float* bs = (const float*)d_in[5];
    const float* Hw = (const float*)d_in[6];
    const float* Hb = (const float*)d_in[7];

    float* out = (float*)d_out;
    float* IA = out + (size_t)Bn * Nn * Dn;  // I_A follows `out` in the tuple

    k_zero_upper<<<256, 256>>>(IA);
    k_gemm<<<dim3(512, 2), 128>>>(feat, W, Hw);
    k_srcdst<<<128, 256>>>(Ws);

    const int smem = (2 * 32 * 256 + 2 * 32 * 36 + 32) * 4;  // 74880 B
    cudaFuncSetAttribute(k_fused, cudaFuncAttributeMaxDynamicSharedMemorySize, smem);
    k_fused<<<512, 256, smem>>>(feat, adj, bb, bs, Hb, out, IA);
}